// round 15
// baseline (speedup 1.0000x reference)
#include <cuda_runtime.h>
#include <cuda_bf16.h>
#include <cuda_fp16.h>
#include <math.h>
#include <stdint.h>

#define B_  2
#define S_  2048
#define H_  2048
#define NH  16
#define NKV 4
#define HD  128
#define KV_DIM (NKV*HD)   // 512
#define M_  (B_*S_)       // 4096
#define NQKV (H_ + 2*KV_DIM)  // 3072

// GEMM operands: fp16, tiled-K layout [K/64][rows][64]
__device__ __half g_xh[M_ * H_],  g_xl[M_ * H_];
__device__ __half g_aoh[M_ * H_], g_aol[M_ * H_];       // written by flash
__device__ __half g_wqkvh[NQKV * H_];                   // weights hi only
__device__ __half g_woh[H_ * H_];
// flash operands (bf16, row-major / transposed)
__device__ __nv_bfloat16 g_Qh[M_ * H_],     g_Ql[M_ * H_];
__device__ __nv_bfloat16 g_Kh[M_ * KV_DIM], g_Kl[M_ * KV_DIM];
__device__ __nv_bfloat16 g_Vth[M_ * KV_DIM], g_Vtl[M_ * KV_DIM];

__device__ __forceinline__ unsigned pack_bf16(float lo, float hi) {
    unsigned d;
    asm("cvt.rn.bf16x2.f32 %0, %1, %2;" : "=r"(d) : "f"(hi), "f"(lo));
    return d;
}
__device__ __forceinline__ unsigned hpack(__half lo, __half hi) {
    return (unsigned)__half_as_ushort(lo) | ((unsigned)__half_as_ushort(hi) << 16);
}
__device__ __forceinline__ unsigned smem_u32(const void* p) {
    return (unsigned)__cvta_generic_to_shared(p);
}

#define LDSM_X4(r0, r1, r2, r3, addr) \
    asm volatile("ldmatrix.sync.aligned.m8n8.x4.shared.b16 {%0,%1,%2,%3}, [%4];" \
        : "=r"(r0), "=r"(r1), "=r"(r2), "=r"(r3) : "r"(addr))

#define CP_ASYNC16(dst, src) \
    asm volatile("cp.async.cg.shared.global [%0], [%1], 16;" :: "r"(dst), "l"(src) : "memory")
#define CP_COMMIT()  asm volatile("cp.async.commit_group;" ::: "memory")
#define CP_WAIT1()   asm volatile("cp.async.wait_group 1;" ::: "memory")

#define MMA_BF16(c, a0,a1,a2,a3, b0,b1) \
    asm volatile( \
        "mma.sync.aligned.m16n8k16.row.col.f32.bf16.bf16.f32 " \
        "{%0,%1,%2,%3}, {%4,%5,%6,%7}, {%8,%9}, {%0,%1,%2,%3};" \
        : "+f"((c)[0]), "+f"((c)[1]), "+f"((c)[2]), "+f"((c)[3]) \
        : "r"(a0), "r"(a1), "r"(a2), "r"(a3), "r"(b0), "r"(b1))

#define MMA_F16(c, a0,a1,a2,a3, b0,b1) \
    asm volatile( \
        "mma.sync.aligned.m16n8k16.row.col.f32.f16.f16.f32 " \
        "{%0,%1,%2,%3}, {%4,%5,%6,%7}, {%8,%9}, {%0,%1,%2,%3};" \
        : "+f"((c)[0]), "+f"((c)[1]), "+f"((c)[2]), "+f"((c)[3]) \
        : "r"(a0), "r"(a1), "r"(a2), "r"(a3), "r"(b0), "r"(b1))

// ---------------------------------------------------------------------------
// Split x into fp16 hi/lo, tiled-K layout [K/64][rows][64]
// ---------------------------------------------------------------------------
__global__ void split_tiled_kernel(const float* __restrict__ in,
                                   __half* __restrict__ hi,
                                   __half* __restrict__ lo, int rows)
{
    int i = blockIdx.x * blockDim.x + threadIdx.x;
    if (i >= rows * H_) return;
    int row = i >> 11;
    int k   = i & 2047;
    float x = in[i];
    __half h = __float2half_rn(x);
    size_t o = (size_t)(k >> 6) * rows * 64 + (size_t)row * 64 + (k & 63);
    hi[o] = h;
    lo[o] = __float2half_rn(x - __half2float(h));
}

// ---------------------------------------------------------------------------
// All weights: transpose, fp16 hi only -> tiled [k/64][n_total][64]
// ---------------------------------------------------------------------------
__global__ void tsplit_all_kernel(const float* __restrict__ wq,
                                  const float* __restrict__ wk,
                                  const float* __restrict__ wv,
                                  const float* __restrict__ wo,
                                  __half* __restrict__ qkvh,
                                  __half* __restrict__ woh_)
{
    const int seg = blockIdx.z;
    const float* W; int N; int n_base; __half* Th; int n_total;
    if (seg == 0)      { W = wq; N = H_;     n_base = 0;           Th = qkvh; n_total = NQKV; }
    else if (seg == 1) { W = wk; N = KV_DIM; n_base = H_;          Th = qkvh; n_total = NQKV; }
    else if (seg == 2) { W = wv; N = KV_DIM; n_base = H_ + KV_DIM; Th = qkvh; n_total = NQKV; }
    else               { W = wo; N = H_;     n_base = 0;           Th = woh_; n_total = H_; }

    const int n0 = blockIdx.x * 32;
    if (n0 >= N) return;
    const int k0 = blockIdx.y * 32;

    __shared__ float tile[32][33];
    const int tx = threadIdx.x, ty = threadIdx.y;
#pragma unroll
    for (int r = 0; r < 32; r += 8)
        tile[ty + r][tx] = W[(size_t)(k0 + ty + r) * N + n0 + tx];
    __syncthreads();
#pragma unroll
    for (int r = 0; r < 32; r += 8) {
        float v = tile[tx][ty + r];
        int k = k0 + tx;
        int n = n_base + n0 + ty + r;
        size_t o = (size_t)(k >> 6) * n_total * 64 + (size_t)n * 64 + (k & 63);
        Th[o] = __float2half_rn(v);
    }
}

// ---------------------------------------------------------------------------
// fp16 2-term GEMM: D = (Ah+Al)·Bh. 256x128 tile, tiled-K, BK=64, 2-stage.
// qkv_mode=1: epilogue rope+split (Q/K, bf16) or transpose+split (V, bf16).
// qkv_mode=0: fp32 C out (WO projection).
// ---------------------------------------------------------------------------
#define A_BYTES  32768u               // 256 rows * 128 B
#define BB_BYTES 16384u               // 128 rows * 128 B
#define STAGE_B  (2u * A_BYTES + BB_BYTES)   // 81920

__global__ __launch_bounds__(256) void fp16x2_gemm_tiled(
    const __half* __restrict__ Ah, const __half* __restrict__ Al,
    const __half* __restrict__ Bh,
    float* __restrict__ outF, int ldcF,
    __nv_bfloat16* __restrict__ qh, __nv_bfloat16* __restrict__ ql,
    __nv_bfloat16* __restrict__ kh, __nv_bfloat16* __restrict__ kl,
    __nv_bfloat16* __restrict__ vth, __nv_bfloat16* __restrict__ vtl,
    const float* __restrict__ rc, const float* __restrict__ rs,
    int qkv_mode, int K, int An, int Bn)
{
    extern __shared__ unsigned char smem_raw[];
    const unsigned sbase = smem_u32(smem_raw);

    const int tid  = threadIdx.x;
    const int lane = tid & 31;
    const int warp = tid >> 5;
    const int g = lane >> 2;
    const int t = lane & 3;
    const int wm = (warp & 3) * 64;
    const int wn = (warp >> 2) * 64;

    const int bx   = blockIdx.x;
    const int brow = blockIdx.y * 256;
    const int bcolB = bx * 128;

    const size_t aStride = (size_t)An * 64;
    const size_t bStride = (size_t)Bn * 64;
    const __half* aBaseH = Ah + (size_t)brow * 64;
    const __half* aBaseL = Al + (size_t)brow * 64;
    const __half* bBaseH = Bh + (size_t)bcolB * 64;

#define LOAD_STAGE(s, ch) do {                                                       \
    const unsigned sb = sbase + (unsigned)(s) * STAGE_B;                             \
    const size_t aoffg = (size_t)(ch) * aStride;                                     \
    const size_t boffg = (size_t)(ch) * bStride;                                     \
    _Pragma("unroll")                                                                \
    for (int i_ = 0; i_ < 8; i_++) {                                                 \
        int u  = tid + i_ * 256;                                                     \
        int r_ = u >> 3;                                                             \
        int c8 = u & 7;                                                              \
        unsigned d_ = (unsigned)(r_ * 128 + (((unsigned)c8 ^ ((unsigned)r_ & 7u)) << 4)); \
        size_t gsrc = (size_t)r_ * 64 + (size_t)c8 * 8;                              \
        CP_ASYNC16(sb + d_,           aBaseH + aoffg + gsrc);                        \
        CP_ASYNC16(sb + A_BYTES + d_, aBaseL + aoffg + gsrc);                        \
    }                                                                                \
    _Pragma("unroll")                                                                \
    for (int i_ = 0; i_ < 4; i_++) {                                                 \
        int u  = tid + i_ * 256;                                                     \
        int r_ = u >> 3;                                                             \
        int c8 = u & 7;                                                              \
        unsigned d_ = (unsigned)(r_ * 128 + (((unsigned)c8 ^ ((unsigned)r_ & 7u)) << 4)); \
        size_t gsrc = (size_t)r_ * 64 + (size_t)c8 * 8;                              \
        CP_ASYNC16(sb + 2 * A_BYTES + d_, bBaseH + boffg + gsrc);                    \
    }                                                                                \
} while (0)

    const unsigned arow   = (unsigned)(wm + (lane & 7) + ((lane >> 3) & 1) * 8);
    const unsigned ahi    = (unsigned)((lane >> 4) & 1);
    const unsigned brow_l = (unsigned)(wn + (lane & 7) + ((lane >> 4) & 1) * 8);
    const unsigned bhi    = (unsigned)((lane >> 3) & 1);

    float acc[4][8][4];
#pragma unroll
    for (int i = 0; i < 4; i++)
#pragma unroll
        for (int j = 0; j < 8; j++)
#pragma unroll
            for (int c = 0; c < 4; c++) acc[i][j][c] = 0.f;

    const int niter = K / 64;
    LOAD_STAGE(0, 0); CP_COMMIT();
    LOAD_STAGE(1, 1); CP_COMMIT();

    for (int it = 0; it < niter; it++) {
        CP_WAIT1();
        __syncthreads();
        const unsigned sb = sbase + (unsigned)(it & 1) * STAGE_B;

#pragma unroll
        for (int ks = 0; ks < 64; ks += 16) {
            const unsigned c16a = (unsigned)(ks >> 3) + ahi;
            const unsigned c16b = (unsigned)(ks >> 3) + bhi;
            unsigned ah[4][4], al[4][4], bh[8][2];
#pragma unroll
            for (int i = 0; i < 4; i++) {
                unsigned ra = arow + (unsigned)(i * 16);
                unsigned ad = sb + ra * 128u + ((c16a ^ (ra & 7u)) << 4);
                LDSM_X4(ah[i][0], ah[i][1], ah[i][2], ah[i][3], ad);
                LDSM_X4(al[i][0], al[i][1], al[i][2], al[i][3], ad + A_BYTES);
            }
#pragma unroll
            for (int jp = 0; jp < 4; jp++) {
                unsigned rb = brow_l + (unsigned)(jp * 16);
                unsigned bd = sb + 2 * A_BYTES + rb * 128u + ((c16b ^ (rb & 7u)) << 4);
                LDSM_X4(bh[2 * jp][0], bh[2 * jp][1], bh[2 * jp + 1][0], bh[2 * jp + 1][1], bd);
            }
#pragma unroll
            for (int i = 0; i < 4; i++)
#pragma unroll
                for (int j = 0; j < 8; j++) {
                    float* c = acc[i][j];
                    MMA_F16(c, ah[i][0], ah[i][1], ah[i][2], ah[i][3], bh[j][0], bh[j][1]);
                    MMA_F16(c, al[i][0], al[i][1], al[i][2], al[i][3], bh[j][0], bh[j][1]);
                }
        }
        __syncthreads();
        if (it + 2 < niter) LOAD_STAGE(it & 1, it + 2);
        CP_COMMIT();
    }
#undef LOAD_STAGE

    if (!qkv_mode) {
#pragma unroll
        for (int i = 0; i < 4; i++) {
            const int r0 = brow + wm + i * 16 + g;
#pragma unroll
            for (int j = 0; j < 8; j++) {
                const int cc = bcolB + wn + j * 8 + 2 * t;
                *(float2*)(outF + (size_t)r0 * ldcF + cc)       = make_float2(acc[i][j][0], acc[i][j][1]);
                *(float2*)(outF + (size_t)(r0 + 8) * ldcF + cc) = make_float2(acc[i][j][2], acc[i][j][3]);
            }
        }
        return;
    }

    // QKV epilogue: exchange acc through smem
    __syncthreads();
    float* sep = (float*)smem_raw;     // [256][132] fp32 = 135168 B <= 163840
#pragma unroll
    for (int i = 0; i < 4; i++) {
        const int r0 = wm + i * 16 + g;
#pragma unroll
        for (int j = 0; j < 8; j++) {
            const int cc = wn + j * 8 + 2 * t;
            sep[r0 * 132 + cc]           = acc[i][j][0];
            sep[r0 * 132 + cc + 1]       = acc[i][j][1];
            sep[(r0 + 8) * 132 + cc]     = acc[i][j][2];
            sep[(r0 + 8) * 132 + cc + 1] = acc[i][j][3];
        }
    }
    __syncthreads();

    if (bx < 20) {
        // Q tiles (bx 0-15) or K tiles (bx 16-19): rope + split, bf16 row-major
        const bool isQ  = bx < 16;
        __nv_bfloat16* Hh = isQ ? qh : kh;
        __nv_bfloat16* Hl = isQ ? ql : kl;
        const int ldo   = isQ ? H_ : KV_DIM;
        const int cbase = isQ ? bx * 128 : (bx - 16) * 128;
        for (int idx = tid; idx < 256 * 32; idx += 256) {
            int r = idx >> 5;
            int d = (idx & 31) * 2;
            int m = brow + r;
            int s = m & (S_ - 1);
            float x1a = sep[r * 132 + d];
            float x1b = sep[r * 132 + d + 1];
            float x2a = sep[r * 132 + d + 64];
            float x2b = sep[r * 132 + d + 65];
            float ca  = rc[s * 64 + d],     cb  = rc[s * 64 + d + 1];
            float sa  = rs[s * 64 + d],     sb_ = rs[s * 64 + d + 1];
            float y1a = x1a * ca - x2a * sa;
            float y1b = x1b * cb - x2b * sb_;
            float y2a = x2a * ca + x1a * sa;
            float y2b = x2b * cb + x1b * sb_;
            unsigned h1 = pack_bf16(y1a, y1b);
            unsigned h2 = pack_bf16(y2a, y2b);
            unsigned l1 = pack_bf16(y1a - __uint_as_float(h1 << 16),
                                    y1b - __uint_as_float(h1 & 0xffff0000u));
            unsigned l2 = pack_bf16(y2a - __uint_as_float(h2 << 16),
                                    y2b - __uint_as_float(h2 & 0xffff0000u));
            size_t o = (size_t)m * ldo + cbase + d;
            *(unsigned*)(Hh + o)      = h1;
            *(unsigned*)(Hl + o)      = l1;
            *(unsigned*)(Hh + o + 64) = h2;
            *(unsigned*)(Hl + o + 64) = l2;
        }
    } else {
        // V tiles (bx 20-23): fused transpose + split -> Vt[(b*NKV+kvh)*HD+d][s]
        const int kvh = bx - 20;
        const int b   = brow >> 11;
        const int s0  = brow & (S_ - 1);
        const int d    = tid >> 1;          // 0..127
        const int half = tid & 1;           // s half
        __nv_bfloat16* Th = vth + (size_t)((b * NKV + kvh) * HD + d) * S_ + s0 + half * 128;
        __nv_bfloat16* Tl = vtl + (size_t)((b * NKV + kvh) * HD + d) * S_ + s0 + half * 128;
        for (int ss = 0; ss < 128; ss += 2) {
            int r = half * 128 + ss;
            float v0 = sep[r * 132 + d];
            float v1 = sep[(r + 1) * 132 + d];
            unsigned hh = pack_bf16(v0, v1);
            unsigned ll = pack_bf16(v0 - __uint_as_float(hh << 16),
                                    v1 - __uint_as_float(hh & 0xffff0000u));
            *(unsigned*)(Th + ss) = hh;
            *(unsigned*)(Tl + ss) = ll;
        }
    }
}

// ---------------------------------------------------------------------------
// Tensor-core flash attention (bf16x3, validated). Epilogue writes fp16
// hi/lo AO in tiled-K layout for the WO GEMM.
// ---------------------------------------------------------------------------
#define KROW 136
#define VROW 72

__global__ __launch_bounds__(256) void flash_mma_kernel(
    const __nv_bfloat16* __restrict__ Qh, const __nv_bfloat16* __restrict__ Ql,
    const __nv_bfloat16* __restrict__ Kh, const __nv_bfloat16* __restrict__ Kl,
    const __nv_bfloat16* __restrict__ Vth, const __nv_bfloat16* __restrict__ Vtl,
    __half* __restrict__ AOh, __half* __restrict__ AOl)
{
    extern __shared__ __nv_bfloat16 smem_bf[];
    __nv_bfloat16* kh = smem_bf;
    __nv_bfloat16* kl = kh + 64 * KROW;
    __nv_bfloat16* vh = kl + 64 * KROW;
    __nv_bfloat16* vl = vh + 128 * VROW;

    const int qb  = (int)gridDim.x - 1 - (int)blockIdx.x;
    const int bh  = blockIdx.y;
    const int b   = bh >> 4;
    const int h   = bh & 15;
    const int kvh = h >> 2;

    const int tid  = threadIdx.x;
    const int lane = tid & 31;
    const int w    = tid >> 5;
    const int g    = lane >> 2;
    const int t    = lane & 3;
    const int m0   = w * 16;

    unsigned qfh[8][4], qfl[8][4];
    {
        const __nv_bfloat16* Qb  = Qh + ((size_t)(b * S_ + qb * 128 + m0)) * H_ + h * HD;
        const __nv_bfloat16* Qlb = Ql + ((size_t)(b * S_ + qb * 128 + m0)) * H_ + h * HD;
#pragma unroll
        for (int kc = 0; kc < 8; kc++) {
            int c0 = kc * 16 + 2 * t;
            qfh[kc][0] = *(const unsigned*)(Qb  + (size_t)g * H_ + c0);
            qfh[kc][1] = *(const unsigned*)(Qb  + (size_t)(g + 8) * H_ + c0);
            qfh[kc][2] = *(const unsigned*)(Qb  + (size_t)g * H_ + c0 + 8);
            qfh[kc][3] = *(const unsigned*)(Qb  + (size_t)(g + 8) * H_ + c0 + 8);
            qfl[kc][0] = *(const unsigned*)(Qlb + (size_t)g * H_ + c0);
            qfl[kc][1] = *(const unsigned*)(Qlb + (size_t)(g + 8) * H_ + c0);
            qfl[kc][2] = *(const unsigned*)(Qlb + (size_t)g * H_ + c0 + 8);
            qfl[kc][3] = *(const unsigned*)(Qlb + (size_t)(g + 8) * H_ + c0 + 8);
        }
    }

    float oacc[16][4];
#pragma unroll
    for (int jn = 0; jn < 16; jn++)
#pragma unroll
        for (int c = 0; c < 4; c++) oacc[jn][c] = 0.f;
    float mrow0 = -INFINITY, mrow1 = -INFINITY;
    float lrow0 = 0.f, lrow1 = 0.f;

    const float scale = 0.08838834764831845f;
    const int njt = 2 * qb + 2;

    for (int j = 0; j < njt; j++) {
        __syncthreads();
        {
            const __nv_bfloat16* Kb  = Kh + (size_t)(b * S_ + j * 64) * KV_DIM + kvh * HD;
            const __nv_bfloat16* Klb = Kl + (size_t)(b * S_ + j * 64) * KV_DIM + kvh * HD;
#pragma unroll
            for (int it = 0; it < 4; it++) {
                int idx = tid + it * 256;
                int r  = idx >> 4;
                int c8 = (idx & 15) * 8;
                *(uint4*)&kh[r * KROW + c8] = *(const uint4*)(Kb  + (size_t)r * KV_DIM + c8);
                *(uint4*)&kl[r * KROW + c8] = *(const uint4*)(Klb + (size_t)r * KV_DIM + c8);
            }
            const __nv_bfloat16* Vb  = Vth + ((size_t)((b * NKV + kvh) * HD)) * S_ + j * 64;
            const __nv_bfloat16* Vlb = Vtl + ((size_t)((b * NKV + kvh) * HD)) * S_ + j * 64;
#pragma unroll
            for (int it = 0; it < 4; it++) {
                int idx = tid + it * 256;
                int r  = idx >> 3;
                int c8 = (idx & 7) * 8;
                *(uint4*)&vh[r * VROW + c8] = *(const uint4*)(Vb  + (size_t)r * S_ + c8);
                *(uint4*)&vl[r * VROW + c8] = *(const uint4*)(Vlb + (size_t)r * S_ + c8);
            }
        }
        __syncthreads();

        float sf[8][4];
#pragma unroll
        for (int jn = 0; jn < 8; jn++)
#pragma unroll
            for (int c = 0; c < 4; c++) sf[jn][c] = 0.f;

#pragma unroll
        for (int jn = 0; jn < 8; jn++) {
            const int n0 = jn * 8;
#pragma unroll
            for (int kc = 0; kc < 8; kc++) {
                const int ck = kc * 16 + 2 * t;
                unsigned b0h = *(const unsigned*)&kh[(n0 + g) * KROW + ck];
                unsigned b1h = *(const unsigned*)&kh[(n0 + g) * KROW + ck + 8];
                unsigned b0l = *(const unsigned*)&kl[(n0 + g) * KROW + ck];
                unsigned b1l = *(const unsigned*)&kl[(n0 + g) * KROW + ck + 8];
                float* c = sf[jn];
                MMA_BF16(c, qfh[kc][0], qfh[kc][1], qfh[kc][2], qfh[kc][3], b0h, b1h);
                MMA_BF16(c, qfh[kc][0], qfh[kc][1], qfh[kc][2], qfh[kc][3], b0l, b1l);
                MMA_BF16(c, qfl[kc][0], qfl[kc][1], qfl[kc][2], qfl[kc][3], b0h, b1h);
            }
        }

        const int row0 = qb * 128 + m0 + g;
        const int row1 = row0 + 8;
        const bool need_mask = (j >= 2 * qb);
#pragma unroll
        for (int jn = 0; jn < 8; jn++) {
            const int cbase = j * 64 + jn * 8 + 2 * t;
#pragma unroll
            for (int c = 0; c < 4; c++) sf[jn][c] *= scale;
            if (need_mask) {
                if (cbase     > row0) sf[jn][0] = -1e30f;
                if (cbase + 1 > row0) sf[jn][1] = -1e30f;
                if (cbase     > row1) sf[jn][2] = -1e30f;
                if (cbase + 1 > row1) sf[jn][3] = -1e30f;
            }
        }

        float mx0 = -INFINITY, mx1 = -INFINITY;
#pragma unroll
        for (int jn = 0; jn < 8; jn++) {
            mx0 = fmaxf(mx0, fmaxf(sf[jn][0], sf[jn][1]));
            mx1 = fmaxf(mx1, fmaxf(sf[jn][2], sf[jn][3]));
        }
        mx0 = fmaxf(mx0, __shfl_xor_sync(0xffffffffu, mx0, 1));
        mx0 = fmaxf(mx0, __shfl_xor_sync(0xffffffffu, mx0, 2));
        mx1 = fmaxf(mx1, __shfl_xor_sync(0xffffffffu, mx1, 1));
        mx1 = fmaxf(mx1, __shfl_xor_sync(0xffffffffu, mx1, 2));
        float mn0 = fmaxf(mrow0, mx0);
        float mn1 = fmaxf(mrow1, mx1);
        float f0 = __expf(mrow0 - mn0);
        float f1 = __expf(mrow1 - mn1);
        mrow0 = mn0; mrow1 = mn1;

        float sum0 = 0.f, sum1 = 0.f;
#pragma unroll
        for (int jn = 0; jn < 8; jn++) {
            sf[jn][0] = __expf(sf[jn][0] - mn0);
            sf[jn][1] = __expf(sf[jn][1] - mn0);
            sf[jn][2] = __expf(sf[jn][2] - mn1);
            sf[jn][3] = __expf(sf[jn][3] - mn1);
            sum0 += sf[jn][0] + sf[jn][1];
            sum1 += sf[jn][2] + sf[jn][3];
        }
        sum0 += __shfl_xor_sync(0xffffffffu, sum0, 1);
        sum0 += __shfl_xor_sync(0xffffffffu, sum0, 2);
        sum1 += __shfl_xor_sync(0xffffffffu, sum1, 1);
        sum1 += __shfl_xor_sync(0xffffffffu, sum1, 2);
        lrow0 = lrow0 * f0 + sum0;
        lrow1 = lrow1 * f1 + sum1;

#pragma unroll
        for (int jn = 0; jn < 16; jn++) {
            oacc[jn][0] *= f0; oacc[jn][1] *= f0;
            oacc[jn][2] *= f1; oacc[jn][3] *= f1;
        }

#pragma unroll
        for (int kc = 0; kc < 4; kc++) {
            const int j0 = 2 * kc, j1 = 2 * kc + 1;
            unsigned a0h = pack_bf16(sf[j0][0], sf[j0][1]);
            unsigned a1h = pack_bf16(sf[j0][2], sf[j0][3]);
            unsigned a2h = pack_bf16(sf[j1][0], sf[j1][1]);
            unsigned a3h = pack_bf16(sf[j1][2], sf[j1][3]);
            unsigned a0l = pack_bf16(sf[j0][0] - __uint_as_float(a0h << 16),
                                     sf[j0][1] - __uint_as_float(a0h & 0xffff0000u));
            unsigned a1l = pack_bf16(sf[j0][2] - __uint_as_float(a1h << 16),
                                     sf[j0][3] - __uint_as_float(a1h & 0xffff0000u));
            unsigned a2l = pack_bf16(sf[j1][0] - __uint_as_float(a2h << 16),
                                     sf[j1][1] - __uint_as_float(a2h & 0xffff0000u));
            unsigned a3l = pack_bf16(sf[j1][2] - __uint_as_float(a3h << 16),
                                     sf[j1][3] - __uint_as_float(a3h & 0xffff0000u));
            const int ck = kc * 16 + 2 * t;
#pragma unroll
            for (int jn = 0; jn < 16; jn++) {
                const int n0 = jn * 8;
                unsigned b0h = *(const unsigned*)&vh[(n0 + g) * VROW + ck];
                unsigned b1h = *(const unsigned*)&vh[(n0 + g) * VROW + ck + 8];
                unsigned b0l = *(const unsigned*)&vl[(n0 + g) * VROW + ck];
                unsigned b1l = *(const unsigned*)&vl[(n0 + g) * VROW + ck + 8];
                float* c = oacc[jn];
                MMA_BF16(c, a0h, a1h, a2h, a3h, b0h, b1h);
                MMA_BF16(c, a0h, a1h, a2h, a3h, b0l, b1l);
                MMA_BF16(c, a0l, a1l, a2l, a3l, b0h, b1h);
            }
        }
    }

    // epilogue: fp16 split + write tiled-K (k = h*128 + jn*8 + 2t)
    {
        float inv0 = 1.f / lrow0;
        float inv1 = 1.f / lrow1;
        const int row0 = b * S_ + qb * 128 + m0 + g;
        const int row1 = row0 + 8;
#pragma unroll
        for (int jn = 0; jn < 16; jn++) {
            int kk = h * HD + jn * 8 + 2 * t;
            int ch = kk >> 6;
            int wi = kk & 63;
            size_t o0 = (size_t)ch * (M_ * 64) + (size_t)row0 * 64 + wi;
            size_t o1 = (size_t)ch * (M_ * 64) + (size_t)row1 * 64 + wi;
            float v0 = oacc[jn][0] * inv0, v1 = oacc[jn][1] * inv0;
            float v2 = oacc[jn][2] * inv1, v3 = oacc[jn][3] * inv1;
            __half h0 = __float2half_rn(v0), h1 = __float2half_rn(v1);
            __half h2 = __float2half_rn(v2), h3 = __float2half_rn(v3);
            __half l0 = __float2half_rn(v0 - __half2float(h0));
            __half l1 = __float2half_rn(v1 - __half2float(h1));
            __half l2 = __float2half_rn(v2 - __half2float(h2));
            __half l3 = __float2half_rn(v3 - __half2float(h3));
            *(unsigned*)(AOh + o0) = hpack(h0, h1);
            *(unsigned*)(AOl + o0) = hpack(l0, l1);
            *(unsigned*)(AOh + o1) = hpack(h2, h3);
            *(unsigned*)(AOl + o1) = hpack(l2, l3);
        }
    }
}

// ---------------------------------------------------------------------------
extern "C" void kernel_launch(void* const* d_in, const int* in_sizes, int n_in,
                              void* d_out, int out_size)
{
    const float* x  = (const float*)d_in[0];
    const float* rc = (const float*)d_in[1];
    const float* rs = (const float*)d_in[2];
    const float* wq = (const float*)d_in[4];
    const float* wk = (const float*)d_in[5];
    const float* wv = (const float*)d_in[6];
    const float* wo = (const float*)d_in[7];
    float* out = (float*)d_out;

    __half *xh, *xl, *aoh, *aol, *wqkvh, *woh;
    __nv_bfloat16 *qh, *ql, *kh, *kl, *vth, *vtl;
    cudaGetSymbolAddress((void**)&xh,  g_xh);
    cudaGetSymbolAddress((void**)&xl,  g_xl);
    cudaGetSymbolAddress((void**)&aoh, g_aoh);
    cudaGetSymbolAddress((void**)&aol, g_aol);
    cudaGetSymbolAddress((void**)&wqkvh, g_wqkvh);
    cudaGetSymbolAddress((void**)&woh, g_woh);
    cudaGetSymbolAddress((void**)&qh,  g_Qh);
    cudaGetSymbolAddress((void**)&ql,  g_Ql);
    cudaGetSymbolAddress((void**)&kh,  g_Kh);
    cudaGetSymbolAddress((void**)&kl,  g_Kl);
    cudaGetSymbolAddress((void**)&vth, g_Vth);
    cudaGetSymbolAddress((void**)&vtl, g_Vtl);

    // Prep
    dim3 tsb(32, 8);
    tsplit_all_kernel<<<dim3(64, 64, 4), tsb>>>(wq, wk, wv, wo, wqkvh, woh);
    split_tiled_kernel<<<(M_ * H_ + 255) / 256, 256>>>(x, xh, xl, M_);

    // Fused QKV projection (fp16 2-term) + rope/split + V transpose epilogue
    const int gemm_smem = 2 * (int)STAGE_B;   // 163840
    cudaFuncSetAttribute(fp16x2_gemm_tiled,
                         cudaFuncAttributeMaxDynamicSharedMemorySize, gemm_smem);
    fp16x2_gemm_tiled<<<dim3(NQKV / 128, M_ / 256), 256, gemm_smem>>>(
        xh, xl, wqkvh,
        nullptr, 0, qh, ql, kh, kl, vth, vtl, rc, rs,
        1, H_, M_, NQKV);

    // Flash attention (bf16x3; writes fp16 tiled AO)
    {
        size_t shmem = (size_t)(2 * 64 * KROW + 2 * 128 * VROW) * sizeof(__nv_bfloat16);
        cudaFuncSetAttribute(flash_mma_kernel,
                             cudaFuncAttributeMaxDynamicSharedMemorySize,
                             (int)shmem);
        flash_mma_kernel<<<dim3(S_ / 128, B_ * NH), 256, shmem>>>(qh, ql, kh, kl, vth, vtl, aoh, aol);
    }

    // Output projection (fp16 2-term, fp32 epilogue)
    fp16x2_gemm_tiled<<<dim3(H_ / 128, M_ / 256), 256, gemm_smem>>>(
        aoh, aol, woh,
        out, H_, nullptr, nullptr, nullptr, nullptr, nullptr, nullptr, nullptr, nullptr,
        0, H_, M_, H_);
}

// round 16
// speedup vs baseline: 1.0004x; 1.0004x over previous
#include <cuda_runtime.h>
#include <cuda_bf16.h>
#include <cuda_fp16.h>
#include <math.h>
#include <stdint.h>

#define B_  2
#define S_  2048
#define H_  2048
#define NH  16
#define NKV 4
#define HD  128
#define KV_DIM (NKV*HD)   // 512
#define M_  (B_*S_)       // 4096
#define NQKV (H_ + 2*KV_DIM)  // 3072

// GEMM operands: fp16, tiled-K layout [K/64][rows][64]
__device__ __half g_xh[M_ * H_],  g_xl[M_ * H_];
__device__ __half g_aoh[M_ * H_], g_aol[M_ * H_];       // written by flash
__device__ __half g_wqkvh[NQKV * H_];                   // weights hi only
__device__ __half g_woh[H_ * H_];
// flash operands (bf16, row-major / transposed)
__device__ __nv_bfloat16 g_Qh[M_ * H_],     g_Ql[M_ * H_];
__device__ __nv_bfloat16 g_Kh[M_ * KV_DIM], g_Kl[M_ * KV_DIM];
__device__ __nv_bfloat16 g_Vth[M_ * KV_DIM], g_Vtl[M_ * KV_DIM];

__device__ __forceinline__ unsigned pack_bf16(float lo, float hi) {
    unsigned d;
    asm("cvt.rn.bf16x2.f32 %0, %1, %2;" : "=r"(d) : "f"(hi), "f"(lo));
    return d;
}
__device__ __forceinline__ unsigned hpack(__half lo, __half hi) {
    return (unsigned)__half_as_ushort(lo) | ((unsigned)__half_as_ushort(hi) << 16);
}
__device__ __forceinline__ unsigned smem_u32(const void* p) {
    return (unsigned)__cvta_generic_to_shared(p);
}

#define LDSM_X4(r0, r1, r2, r3, addr) \
    asm volatile("ldmatrix.sync.aligned.m8n8.x4.shared.b16 {%0,%1,%2,%3}, [%4];" \
        : "=r"(r0), "=r"(r1), "=r"(r2), "=r"(r3) : "r"(addr))

#define CP_ASYNC16(dst, src) \
    asm volatile("cp.async.cg.shared.global [%0], [%1], 16;" :: "r"(dst), "l"(src) : "memory")
#define CP_COMMIT()  asm volatile("cp.async.commit_group;" ::: "memory")
#define CP_WAIT1()   asm volatile("cp.async.wait_group 1;" ::: "memory")

#define MMA_BF16(c, a0,a1,a2,a3, b0,b1) \
    asm volatile( \
        "mma.sync.aligned.m16n8k16.row.col.f32.bf16.bf16.f32 " \
        "{%0,%1,%2,%3}, {%4,%5,%6,%7}, {%8,%9}, {%0,%1,%2,%3};" \
        : "+f"((c)[0]), "+f"((c)[1]), "+f"((c)[2]), "+f"((c)[3]) \
        : "r"(a0), "r"(a1), "r"(a2), "r"(a3), "r"(b0), "r"(b1))

#define MMA_F16(c, a0,a1,a2,a3, b0,b1) \
    asm volatile( \
        "mma.sync.aligned.m16n8k16.row.col.f32.f16.f16.f32 " \
        "{%0,%1,%2,%3}, {%4,%5,%6,%7}, {%8,%9}, {%0,%1,%2,%3};" \
        : "+f"((c)[0]), "+f"((c)[1]), "+f"((c)[2]), "+f"((c)[3]) \
        : "r"(a0), "r"(a1), "r"(a2), "r"(a3), "r"(b0), "r"(b1))

// ---------------------------------------------------------------------------
// Split x into fp16 hi/lo, tiled-K layout [K/64][rows][64]
// ---------------------------------------------------------------------------
__global__ void split_tiled_kernel(const float* __restrict__ in,
                                   __half* __restrict__ hi,
                                   __half* __restrict__ lo, int rows)
{
    int i = blockIdx.x * blockDim.x + threadIdx.x;
    if (i >= rows * H_) return;
    int row = i >> 11;
    int k   = i & 2047;
    float x = in[i];
    __half h = __float2half_rn(x);
    size_t o = (size_t)(k >> 6) * rows * 64 + (size_t)row * 64 + (k & 63);
    hi[o] = h;
    lo[o] = __float2half_rn(x - __half2float(h));
}

// ---------------------------------------------------------------------------
// All weights: transpose, fp16 hi only -> tiled [k/64][n_total][64]
// ---------------------------------------------------------------------------
__global__ void tsplit_all_kernel(const float* __restrict__ wq,
                                  const float* __restrict__ wk,
                                  const float* __restrict__ wv,
                                  const float* __restrict__ wo,
                                  __half* __restrict__ qkvh,
                                  __half* __restrict__ woh_)
{
    const int seg = blockIdx.z;
    const float* W; int N; int n_base; __half* Th; int n_total;
    if (seg == 0)      { W = wq; N = H_;     n_base = 0;           Th = qkvh; n_total = NQKV; }
    else if (seg == 1) { W = wk; N = KV_DIM; n_base = H_;          Th = qkvh; n_total = NQKV; }
    else if (seg == 2) { W = wv; N = KV_DIM; n_base = H_ + KV_DIM; Th = qkvh; n_total = NQKV; }
    else               { W = wo; N = H_;     n_base = 0;           Th = woh_; n_total = H_; }

    const int n0 = blockIdx.x * 32;
    if (n0 >= N) return;
    const int k0 = blockIdx.y * 32;

    __shared__ float tile[32][33];
    const int tx = threadIdx.x, ty = threadIdx.y;
#pragma unroll
    for (int r = 0; r < 32; r += 8)
        tile[ty + r][tx] = W[(size_t)(k0 + ty + r) * N + n0 + tx];
    __syncthreads();
#pragma unroll
    for (int r = 0; r < 32; r += 8) {
        float v = tile[tx][ty + r];
        int k = k0 + tx;
        int n = n_base + n0 + ty + r;
        size_t o = (size_t)(k >> 6) * n_total * 64 + (size_t)n * 64 + (k & 63);
        Th[o] = __float2half_rn(v);
    }
}

// ---------------------------------------------------------------------------
// fp16 2-term GEMM: D = (Ah+Al)·Bh. 256x128 tile, tiled-K, BK=64, 2-stage.
// qkv_mode=1: epilogue rope+split (Q/K, bf16) or transpose+split (V, bf16).
// qkv_mode=0: fp32 C out (WO projection).
// ---------------------------------------------------------------------------
#define A_BYTES  32768u               // 256 rows * 128 B
#define BB_BYTES 16384u               // 128 rows * 128 B
#define STAGE_B  (2u * A_BYTES + BB_BYTES)   // 81920

__global__ __launch_bounds__(256) void fp16x2_gemm_tiled(
    const __half* __restrict__ Ah, const __half* __restrict__ Al,
    const __half* __restrict__ Bh,
    float* __restrict__ outF, int ldcF,
    __nv_bfloat16* __restrict__ qh, __nv_bfloat16* __restrict__ ql,
    __nv_bfloat16* __restrict__ kh, __nv_bfloat16* __restrict__ kl,
    __nv_bfloat16* __restrict__ vth, __nv_bfloat16* __restrict__ vtl,
    const float* __restrict__ rc, const float* __restrict__ rs,
    int qkv_mode, int K, int An, int Bn)
{
    extern __shared__ unsigned char smem_raw[];
    const unsigned sbase = smem_u32(smem_raw);

    const int tid  = threadIdx.x;
    const int lane = tid & 31;
    const int warp = tid >> 5;
    const int g = lane >> 2;
    const int t = lane & 3;
    const int wm = (warp & 3) * 64;
    const int wn = (warp >> 2) * 64;

    const int bx   = blockIdx.x;
    const int brow = blockIdx.y * 256;
    const int bcolB = bx * 128;

    const size_t aStride = (size_t)An * 64;
    const size_t bStride = (size_t)Bn * 64;
    const __half* aBaseH = Ah + (size_t)brow * 64;
    const __half* aBaseL = Al + (size_t)brow * 64;
    const __half* bBaseH = Bh + (size_t)bcolB * 64;

#define LOAD_STAGE(s, ch) do {                                                       \
    const unsigned sb = sbase + (unsigned)(s) * STAGE_B;                             \
    const size_t aoffg = (size_t)(ch) * aStride;                                     \
    const size_t boffg = (size_t)(ch) * bStride;                                     \
    _Pragma("unroll")                                                                \
    for (int i_ = 0; i_ < 8; i_++) {                                                 \
        int u  = tid + i_ * 256;                                                     \
        int r_ = u >> 3;                                                             \
        int c8 = u & 7;                                                              \
        unsigned d_ = (unsigned)(r_ * 128 + (((unsigned)c8 ^ ((unsigned)r_ & 7u)) << 4)); \
        size_t gsrc = (size_t)r_ * 64 + (size_t)c8 * 8;                              \
        CP_ASYNC16(sb + d_,           aBaseH + aoffg + gsrc);                        \
        CP_ASYNC16(sb + A_BYTES + d_, aBaseL + aoffg + gsrc);                        \
    }                                                                                \
    _Pragma("unroll")                                                                \
    for (int i_ = 0; i_ < 4; i_++) {                                                 \
        int u  = tid + i_ * 256;                                                     \
        int r_ = u >> 3;                                                             \
        int c8 = u & 7;                                                              \
        unsigned d_ = (unsigned)(r_ * 128 + (((unsigned)c8 ^ ((unsigned)r_ & 7u)) << 4)); \
        size_t gsrc = (size_t)r_ * 64 + (size_t)c8 * 8;                              \
        CP_ASYNC16(sb + 2 * A_BYTES + d_, bBaseH + boffg + gsrc);                    \
    }                                                                                \
} while (0)

    const unsigned arow   = (unsigned)(wm + (lane & 7) + ((lane >> 3) & 1) * 8);
    const unsigned ahi    = (unsigned)((lane >> 4) & 1);
    const unsigned brow_l = (unsigned)(wn + (lane & 7) + ((lane >> 4) & 1) * 8);
    const unsigned bhi    = (unsigned)((lane >> 3) & 1);

    float acc[4][8][4];
#pragma unroll
    for (int i = 0; i < 4; i++)
#pragma unroll
        for (int j = 0; j < 8; j++)
#pragma unroll
            for (int c = 0; c < 4; c++) acc[i][j][c] = 0.f;

    const int niter = K / 64;
    LOAD_STAGE(0, 0); CP_COMMIT();
    LOAD_STAGE(1, 1); CP_COMMIT();

    for (int it = 0; it < niter; it++) {
        CP_WAIT1();
        __syncthreads();
        const unsigned sb = sbase + (unsigned)(it & 1) * STAGE_B;

#pragma unroll
        for (int ks = 0; ks < 64; ks += 16) {
            const unsigned c16a = (unsigned)(ks >> 3) + ahi;
            const unsigned c16b = (unsigned)(ks >> 3) + bhi;
            unsigned ah[4][4], al[4][4], bh[8][2];
#pragma unroll
            for (int i = 0; i < 4; i++) {
                unsigned ra = arow + (unsigned)(i * 16);
                unsigned ad = sb + ra * 128u + ((c16a ^ (ra & 7u)) << 4);
                LDSM_X4(ah[i][0], ah[i][1], ah[i][2], ah[i][3], ad);
                LDSM_X4(al[i][0], al[i][1], al[i][2], al[i][3], ad + A_BYTES);
            }
#pragma unroll
            for (int jp = 0; jp < 4; jp++) {
                unsigned rb = brow_l + (unsigned)(jp * 16);
                unsigned bd = sb + 2 * A_BYTES + rb * 128u + ((c16b ^ (rb & 7u)) << 4);
                LDSM_X4(bh[2 * jp][0], bh[2 * jp][1], bh[2 * jp + 1][0], bh[2 * jp + 1][1], bd);
            }
#pragma unroll
            for (int i = 0; i < 4; i++)
#pragma unroll
                for (int j = 0; j < 8; j++) {
                    float* c = acc[i][j];
                    MMA_F16(c, ah[i][0], ah[i][1], ah[i][2], ah[i][3], bh[j][0], bh[j][1]);
                    MMA_F16(c, al[i][0], al[i][1], al[i][2], al[i][3], bh[j][0], bh[j][1]);
                }
        }
        __syncthreads();
        if (it + 2 < niter) LOAD_STAGE(it & 1, it + 2);
        CP_COMMIT();
    }
#undef LOAD_STAGE

    if (!qkv_mode) {
#pragma unroll
        for (int i = 0; i < 4; i++) {
            const int r0 = brow + wm + i * 16 + g;
#pragma unroll
            for (int j = 0; j < 8; j++) {
                const int cc = bcolB + wn + j * 8 + 2 * t;
                *(float2*)(outF + (size_t)r0 * ldcF + cc)       = make_float2(acc[i][j][0], acc[i][j][1]);
                *(float2*)(outF + (size_t)(r0 + 8) * ldcF + cc) = make_float2(acc[i][j][2], acc[i][j][3]);
            }
        }
        return;
    }

    // QKV epilogue: exchange acc through smem
    __syncthreads();
    float* sep = (float*)smem_raw;     // [256][132] fp32 = 135168 B <= 163840
#pragma unroll
    for (int i = 0; i < 4; i++) {
        const int r0 = wm + i * 16 + g;
#pragma unroll
        for (int j = 0; j < 8; j++) {
            const int cc = wn + j * 8 + 2 * t;
            sep[r0 * 132 + cc]           = acc[i][j][0];
            sep[r0 * 132 + cc + 1]       = acc[i][j][1];
            sep[(r0 + 8) * 132 + cc]     = acc[i][j][2];
            sep[(r0 + 8) * 132 + cc + 1] = acc[i][j][3];
        }
    }
    __syncthreads();

    if (bx < 20) {
        // Q tiles (bx 0-15) or K tiles (bx 16-19): rope + split, bf16 row-major
        const bool isQ  = bx < 16;
        __nv_bfloat16* Hh = isQ ? qh : kh;
        __nv_bfloat16* Hl = isQ ? ql : kl;
        const int ldo   = isQ ? H_ : KV_DIM;
        const int cbase = isQ ? bx * 128 : (bx - 16) * 128;
        for (int idx = tid; idx < 256 * 32; idx += 256) {
            int r = idx >> 5;
            int d = (idx & 31) * 2;
            int m = brow + r;
            int s = m & (S_ - 1);
            float x1a = sep[r * 132 + d];
            float x1b = sep[r * 132 + d + 1];
            float x2a = sep[r * 132 + d + 64];
            float x2b = sep[r * 132 + d + 65];
            float ca  = rc[s * 64 + d],     cb  = rc[s * 64 + d + 1];
            float sa  = rs[s * 64 + d],     sb_ = rs[s * 64 + d + 1];
            float y1a = x1a * ca - x2a * sa;
            float y1b = x1b * cb - x2b * sb_;
            float y2a = x2a * ca + x1a * sa;
            float y2b = x2b * cb + x1b * sb_;
            unsigned h1 = pack_bf16(y1a, y1b);
            unsigned h2 = pack_bf16(y2a, y2b);
            unsigned l1 = pack_bf16(y1a - __uint_as_float(h1 << 16),
                                    y1b - __uint_as_float(h1 & 0xffff0000u));
            unsigned l2 = pack_bf16(y2a - __uint_as_float(h2 << 16),
                                    y2b - __uint_as_float(h2 & 0xffff0000u));
            size_t o = (size_t)m * ldo + cbase + d;
            *(unsigned*)(Hh + o)      = h1;
            *(unsigned*)(Hl + o)      = l1;
            *(unsigned*)(Hh + o + 64) = h2;
            *(unsigned*)(Hl + o + 64) = l2;
        }
    } else {
        // V tiles (bx 20-23): fused transpose + split -> Vt[(b*NKV+kvh)*HD+d][s]
        const int kvh = bx - 20;
        const int b   = brow >> 11;
        const int s0  = brow & (S_ - 1);
        const int d    = tid >> 1;          // 0..127
        const int half = tid & 1;           // s half
        __nv_bfloat16* Th = vth + (size_t)((b * NKV + kvh) * HD + d) * S_ + s0 + half * 128;
        __nv_bfloat16* Tl = vtl + (size_t)((b * NKV + kvh) * HD + d) * S_ + s0 + half * 128;
        for (int ss = 0; ss < 128; ss += 2) {
            int r = half * 128 + ss;
            float v0 = sep[r * 132 + d];
            float v1 = sep[(r + 1) * 132 + d];
            unsigned hh = pack_bf16(v0, v1);
            unsigned ll = pack_bf16(v0 - __uint_as_float(hh << 16),
                                    v1 - __uint_as_float(hh & 0xffff0000u));
            *(unsigned*)(Th + ss) = hh;
            *(unsigned*)(Tl + ss) = ll;
        }
    }
}

// ---------------------------------------------------------------------------
// Tensor-core flash attention (bf16x3, validated). Epilogue writes fp16
// hi/lo AO in tiled-K layout for the WO GEMM.
// ---------------------------------------------------------------------------
#define KROW 136
#define VROW 72

__global__ __launch_bounds__(256) void flash_mma_kernel(
    const __nv_bfloat16* __restrict__ Qh, const __nv_bfloat16* __restrict__ Ql,
    const __nv_bfloat16* __restrict__ Kh, const __nv_bfloat16* __restrict__ Kl,
    const __nv_bfloat16* __restrict__ Vth, const __nv_bfloat16* __restrict__ Vtl,
    __half* __restrict__ AOh, __half* __restrict__ AOl)
{
    extern __shared__ __nv_bfloat16 smem_bf[];
    __nv_bfloat16* kh = smem_bf;
    __nv_bfloat16* kl = kh + 64 * KROW;
    __nv_bfloat16* vh = kl + 64 * KROW;
    __nv_bfloat16* vl = vh + 128 * VROW;

    const int qb  = (int)gridDim.x - 1 - (int)blockIdx.x;
    const int bh  = blockIdx.y;
    const int b   = bh >> 4;
    const int h   = bh & 15;
    const int kvh = h >> 2;

    const int tid  = threadIdx.x;
    const int lane = tid & 31;
    const int w    = tid >> 5;
    const int g    = lane >> 2;
    const int t    = lane & 3;
    const int m0   = w * 16;

    unsigned qfh[8][4], qfl[8][4];
    {
        const __nv_bfloat16* Qb  = Qh + ((size_t)(b * S_ + qb * 128 + m0)) * H_ + h * HD;
        const __nv_bfloat16* Qlb = Ql + ((size_t)(b * S_ + qb * 128 + m0)) * H_ + h * HD;
#pragma unroll
        for (int kc = 0; kc < 8; kc++) {
            int c0 = kc * 16 + 2 * t;
            qfh[kc][0] = *(const unsigned*)(Qb  + (size_t)g * H_ + c0);
            qfh[kc][1] = *(const unsigned*)(Qb  + (size_t)(g + 8) * H_ + c0);
            qfh[kc][2] = *(const unsigned*)(Qb  + (size_t)g * H_ + c0 + 8);
            qfh[kc][3] = *(const unsigned*)(Qb  + (size_t)(g + 8) * H_ + c0 + 8);
            qfl[kc][0] = *(const unsigned*)(Qlb + (size_t)g * H_ + c0);
            qfl[kc][1] = *(const unsigned*)(Qlb + (size_t)(g + 8) * H_ + c0);
            qfl[kc][2] = *(const unsigned*)(Qlb + (size_t)g * H_ + c0 + 8);
            qfl[kc][3] = *(const unsigned*)(Qlb + (size_t)(g + 8) * H_ + c0 + 8);
        }
    }

    float oacc[16][4];
#pragma unroll
    for (int jn = 0; jn < 16; jn++)
#pragma unroll
        for (int c = 0; c < 4; c++) oacc[jn][c] = 0.f;
    float mrow0 = -INFINITY, mrow1 = -INFINITY;
    float lrow0 = 0.f, lrow1 = 0.f;

    const float scale = 0.08838834764831845f;
    const int njt = 2 * qb + 2;

    for (int j = 0; j < njt; j++) {
        __syncthreads();
        {
            const __nv_bfloat16* Kb  = Kh + (size_t)(b * S_ + j * 64) * KV_DIM + kvh * HD;
            const __nv_bfloat16* Klb = Kl + (size_t)(b * S_ + j * 64) * KV_DIM + kvh * HD;
#pragma unroll
            for (int it = 0; it < 4; it++) {
                int idx = tid + it * 256;
                int r  = idx >> 4;
                int c8 = (idx & 15) * 8;
                *(uint4*)&kh[r * KROW + c8] = *(const uint4*)(Kb  + (size_t)r * KV_DIM + c8);
                *(uint4*)&kl[r * KROW + c8] = *(const uint4*)(Klb + (size_t)r * KV_DIM + c8);
            }
            const __nv_bfloat16* Vb  = Vth + ((size_t)((b * NKV + kvh) * HD)) * S_ + j * 64;
            const __nv_bfloat16* Vlb = Vtl + ((size_t)((b * NKV + kvh) * HD)) * S_ + j * 64;
#pragma unroll
            for (int it = 0; it < 4; it++) {
                int idx = tid + it * 256;
                int r  = idx >> 3;
                int c8 = (idx & 7) * 8;
                *(uint4*)&vh[r * VROW + c8] = *(const uint4*)(Vb  + (size_t)r * S_ + c8);
                *(uint4*)&vl[r * VROW + c8] = *(const uint4*)(Vlb + (size_t)r * S_ + c8);
            }
        }
        __syncthreads();

        float sf[8][4];
#pragma unroll
        for (int jn = 0; jn < 8; jn++)
#pragma unroll
            for (int c = 0; c < 4; c++) sf[jn][c] = 0.f;

#pragma unroll
        for (int jn = 0; jn < 8; jn++) {
            const int n0 = jn * 8;
#pragma unroll
            for (int kc = 0; kc < 8; kc++) {
                const int ck = kc * 16 + 2 * t;
                unsigned b0h = *(const unsigned*)&kh[(n0 + g) * KROW + ck];
                unsigned b1h = *(const unsigned*)&kh[(n0 + g) * KROW + ck + 8];
                unsigned b0l = *(const unsigned*)&kl[(n0 + g) * KROW + ck];
                unsigned b1l = *(const unsigned*)&kl[(n0 + g) * KROW + ck + 8];
                float* c = sf[jn];
                MMA_BF16(c, qfh[kc][0], qfh[kc][1], qfh[kc][2], qfh[kc][3], b0h, b1h);
                MMA_BF16(c, qfh[kc][0], qfh[kc][1], qfh[kc][2], qfh[kc][3], b0l, b1l);
                MMA_BF16(c, qfl[kc][0], qfl[kc][1], qfl[kc][2], qfl[kc][3], b0h, b1h);
            }
        }

        const int row0 = qb * 128 + m0 + g;
        const int row1 = row0 + 8;
        const bool need_mask = (j >= 2 * qb);
#pragma unroll
        for (int jn = 0; jn < 8; jn++) {
            const int cbase = j * 64 + jn * 8 + 2 * t;
#pragma unroll
            for (int c = 0; c < 4; c++) sf[jn][c] *= scale;
            if (need_mask) {
                if (cbase     > row0) sf[jn][0] = -1e30f;
                if (cbase + 1 > row0) sf[jn][1] = -1e30f;
                if (cbase     > row1) sf[jn][2] = -1e30f;
                if (cbase + 1 > row1) sf[jn][3] = -1e30f;
            }
        }

        float mx0 = -INFINITY, mx1 = -INFINITY;
#pragma unroll
        for (int jn = 0; jn < 8; jn++) {
            mx0 = fmaxf(mx0, fmaxf(sf[jn][0], sf[jn][1]));
            mx1 = fmaxf(mx1, fmaxf(sf[jn][2], sf[jn][3]));
        }
        mx0 = fmaxf(mx0, __shfl_xor_sync(0xffffffffu, mx0, 1));
        mx0 = fmaxf(mx0, __shfl_xor_sync(0xffffffffu, mx0, 2));
        mx1 = fmaxf(mx1, __shfl_xor_sync(0xffffffffu, mx1, 1));
        mx1 = fmaxf(mx1, __shfl_xor_sync(0xffffffffu, mx1, 2));
        float mn0 = fmaxf(mrow0, mx0);
        float mn1 = fmaxf(mrow1, mx1);
        float f0 = __expf(mrow0 - mn0);
        float f1 = __expf(mrow1 - mn1);
        mrow0 = mn0; mrow1 = mn1;

        float sum0 = 0.f, sum1 = 0.f;
#pragma unroll
        for (int jn = 0; jn < 8; jn++) {
            sf[jn][0] = __expf(sf[jn][0] - mn0);
            sf[jn][1] = __expf(sf[jn][1] - mn0);
            sf[jn][2] = __expf(sf[jn][2] - mn1);
            sf[jn][3] = __expf(sf[jn][3] - mn1);
            sum0 += sf[jn][0] + sf[jn][1];
            sum1 += sf[jn][2] + sf[jn][3];
        }
        sum0 += __shfl_xor_sync(0xffffffffu, sum0, 1);
        sum0 += __shfl_xor_sync(0xffffffffu, sum0, 2);
        sum1 += __shfl_xor_sync(0xffffffffu, sum1, 1);
        sum1 += __shfl_xor_sync(0xffffffffu, sum1, 2);
        lrow0 = lrow0 * f0 + sum0;
        lrow1 = lrow1 * f1 + sum1;

#pragma unroll
        for (int jn = 0; jn < 16; jn++) {
            oacc[jn][0] *= f0; oacc[jn][1] *= f0;
            oacc[jn][2] *= f1; oacc[jn][3] *= f1;
        }

#pragma unroll
        for (int kc = 0; kc < 4; kc++) {
            const int j0 = 2 * kc, j1 = 2 * kc + 1;
            unsigned a0h = pack_bf16(sf[j0][0], sf[j0][1]);
            unsigned a1h = pack_bf16(sf[j0][2], sf[j0][3]);
            unsigned a2h = pack_bf16(sf[j1][0], sf[j1][1]);
            unsigned a3h = pack_bf16(sf[j1][2], sf[j1][3]);
            unsigned a0l = pack_bf16(sf[j0][0] - __uint_as_float(a0h << 16),
                                     sf[j0][1] - __uint_as_float(a0h & 0xffff0000u));
            unsigned a1l = pack_bf16(sf[j0][2] - __uint_as_float(a1h << 16),
                                     sf[j0][3] - __uint_as_float(a1h & 0xffff0000u));
            unsigned a2l = pack_bf16(sf[j1][0] - __uint_as_float(a2h << 16),
                                     sf[j1][1] - __uint_as_float(a2h & 0xffff0000u));
            unsigned a3l = pack_bf16(sf[j1][2] - __uint_as_float(a3h << 16),
                                     sf[j1][3] - __uint_as_float(a3h & 0xffff0000u));
            const int ck = kc * 16 + 2 * t;
#pragma unroll
            for (int jn = 0; jn < 16; jn++) {
                const int n0 = jn * 8;
                unsigned b0h = *(const unsigned*)&vh[(n0 + g) * VROW + ck];
                unsigned b1h = *(const unsigned*)&vh[(n0 + g) * VROW + ck + 8];
                unsigned b0l = *(const unsigned*)&vl[(n0 + g) * VROW + ck];
                unsigned b1l = *(const unsigned*)&vl[(n0 + g) * VROW + ck + 8];
                float* c = oacc[jn];
                MMA_BF16(c, a0h, a1h, a2h, a3h, b0h, b1h);
                MMA_BF16(c, a0h, a1h, a2h, a3h, b0l, b1l);
                MMA_BF16(c, a0l, a1l, a2l, a3l, b0h, b1h);
            }
        }
    }

    // epilogue: fp16 split + write tiled-K (k = h*128 + jn*8 + 2t)
    {
        float inv0 = 1.f / lrow0;
        float inv1 = 1.f / lrow1;
        const int row0 = b * S_ + qb * 128 + m0 + g;
        const int row1 = row0 + 8;
#pragma unroll
        for (int jn = 0; jn < 16; jn++) {
            int kk = h * HD + jn * 8 + 2 * t;
            int ch = kk >> 6;
            int wi = kk & 63;
            size_t o0 = (size_t)ch * (M_ * 64) + (size_t)row0 * 64 + wi;
            size_t o1 = (size_t)ch * (M_ * 64) + (size_t)row1 * 64 + wi;
            float v0 = oacc[jn][0] * inv0, v1 = oacc[jn][1] * inv0;
            float v2 = oacc[jn][2] * inv1, v3 = oacc[jn][3] * inv1;
            __half h0 = __float2half_rn(v0), h1 = __float2half_rn(v1);
            __half h2 = __float2half_rn(v2), h3 = __float2half_rn(v3);
            __half l0 = __float2half_rn(v0 - __half2float(h0));
            __half l1 = __float2half_rn(v1 - __half2float(h1));
            __half l2 = __float2half_rn(v2 - __half2float(h2));
            __half l3 = __float2half_rn(v3 - __half2float(h3));
            *(unsigned*)(AOh + o0) = hpack(h0, h1);
            *(unsigned*)(AOl + o0) = hpack(l0, l1);
            *(unsigned*)(AOh + o1) = hpack(h2, h3);
            *(unsigned*)(AOl + o1) = hpack(l2, l3);
        }
    }
}

// ---------------------------------------------------------------------------
extern "C" void kernel_launch(void* const* d_in, const int* in_sizes, int n_in,
                              void* d_out, int out_size)
{
    const float* x  = (const float*)d_in[0];
    const float* rc = (const float*)d_in[1];
    const float* rs = (const float*)d_in[2];
    const float* wq = (const float*)d_in[4];
    const float* wk = (const float*)d_in[5];
    const float* wv = (const float*)d_in[6];
    const float* wo = (const float*)d_in[7];
    float* out = (float*)d_out;

    __half *xh, *xl, *aoh, *aol, *wqkvh, *woh;
    __nv_bfloat16 *qh, *ql, *kh, *kl, *vth, *vtl;
    cudaGetSymbolAddress((void**)&xh,  g_xh);
    cudaGetSymbolAddress((void**)&xl,  g_xl);
    cudaGetSymbolAddress((void**)&aoh, g_aoh);
    cudaGetSymbolAddress((void**)&aol, g_aol);
    cudaGetSymbolAddress((void**)&wqkvh, g_wqkvh);
    cudaGetSymbolAddress((void**)&woh, g_woh);
    cudaGetSymbolAddress((void**)&qh,  g_Qh);
    cudaGetSymbolAddress((void**)&ql,  g_Ql);
    cudaGetSymbolAddress((void**)&kh,  g_Kh);
    cudaGetSymbolAddress((void**)&kl,  g_Kl);
    cudaGetSymbolAddress((void**)&vth, g_Vth);
    cudaGetSymbolAddress((void**)&vtl, g_Vtl);

    // Prep
    dim3 tsb(32, 8);
    tsplit_all_kernel<<<dim3(64, 64, 4), tsb>>>(wq, wk, wv, wo, wqkvh, woh);
    split_tiled_kernel<<<(M_ * H_ + 255) / 256, 256>>>(x, xh, xl, M_);

    // Fused QKV projection (fp16 2-term) + rope/split + V transpose epilogue
    const int gemm_smem = 2 * (int)STAGE_B;   // 163840
    cudaFuncSetAttribute(fp16x2_gemm_tiled,
                         cudaFuncAttributeMaxDynamicSharedMemorySize, gemm_smem);
    fp16x2_gemm_tiled<<<dim3(NQKV / 128, M_ / 256), 256, gemm_smem>>>(
        xh, xl, wqkvh,
        nullptr, 0, qh, ql, kh, kl, vth, vtl, rc, rs,
        1, H_, M_, NQKV);

    // Flash attention (bf16x3; writes fp16 tiled AO)
    {
        size_t shmem = (size_t)(2 * 64 * KROW + 2 * 128 * VROW) * sizeof(__nv_bfloat16);
        cudaFuncSetAttribute(flash_mma_kernel,
                             cudaFuncAttributeMaxDynamicSharedMemorySize,
                             (int)shmem);
        flash_mma_kernel<<<dim3(S_ / 128, B_ * NH), 256, shmem>>>(qh, ql, kh, kl, vth, vtl, aoh, aol);
    }

    // Output projection (fp16 2-term, fp32 epilogue)
    fp16x2_gemm_tiled<<<dim3(H_ / 128, M_ / 256), 256, gemm_smem>>>(
        aoh, aol, woh,
        out, H_, nullptr, nullptr, nullptr, nullptr, nullptr, nullptr, nullptr, nullptr,
        0, H_, M_, H_);
}

// round 17
// speedup vs baseline: 1.1212x; 1.1207x over previous
#include <cuda_runtime.h>
#include <cuda_bf16.h>
#include <cuda_fp16.h>
#include <math.h>
#include <stdint.h>

#define B_  2
#define S_  2048
#define H_  2048
#define NH  16
#define NKV 4
#define HD  128
#define KV_DIM (NKV*HD)   // 512
#define M_  (B_*S_)       // 4096
#define NQKV (H_ + 2*KV_DIM)  // 3072

// GEMM operands: fp16, tiled-K layout [K/64][rows][64]
__device__ __half g_xh[M_ * H_],  g_xl[M_ * H_];
__device__ __half g_aoh[M_ * H_], g_aol[M_ * H_];       // written by flash
__device__ __half g_wqkvh[NQKV * H_];                   // weights hi only
__device__ __half g_woh[H_ * H_];
// flash operands (fp16): Q hi/lo row-major; K hi row-major; Vt hi transposed
__device__ __half g_Qh[M_ * H_], g_Ql[M_ * H_];
__device__ __half g_Kh[M_ * KV_DIM];
__device__ __half g_Vth[M_ * KV_DIM];

__device__ __forceinline__ unsigned hpack(__half lo, __half hi) {
    return (unsigned)__half_as_ushort(lo) | ((unsigned)__half_as_ushort(hi) << 16);
}
__device__ __forceinline__ unsigned hpack_f(float lo, float hi) {
    return hpack(__float2half_rn(lo), __float2half_rn(hi));
}
__device__ __forceinline__ unsigned smem_u32(const void* p) {
    return (unsigned)__cvta_generic_to_shared(p);
}

#define LDSM_X4(r0, r1, r2, r3, addr) \
    asm volatile("ldmatrix.sync.aligned.m8n8.x4.shared.b16 {%0,%1,%2,%3}, [%4];" \
        : "=r"(r0), "=r"(r1), "=r"(r2), "=r"(r3) : "r"(addr))

#define CP_ASYNC16(dst, src) \
    asm volatile("cp.async.cg.shared.global [%0], [%1], 16;" :: "r"(dst), "l"(src) : "memory")
#define CP_COMMIT()  asm volatile("cp.async.commit_group;" ::: "memory")
#define CP_WAIT1()   asm volatile("cp.async.wait_group 1;" ::: "memory")

#define MMA_F16(c, a0,a1,a2,a3, b0,b1) \
    asm volatile( \
        "mma.sync.aligned.m16n8k16.row.col.f32.f16.f16.f32 " \
        "{%0,%1,%2,%3}, {%4,%5,%6,%7}, {%8,%9}, {%0,%1,%2,%3};" \
        : "+f"((c)[0]), "+f"((c)[1]), "+f"((c)[2]), "+f"((c)[3]) \
        : "r"(a0), "r"(a1), "r"(a2), "r"(a3), "r"(b0), "r"(b1))

// ---------------------------------------------------------------------------
// Split x into fp16 hi/lo, tiled-K layout [K/64][rows][64]
// ---------------------------------------------------------------------------
__global__ void split_tiled_kernel(const float* __restrict__ in,
                                   __half* __restrict__ hi,
                                   __half* __restrict__ lo, int rows)
{
    int i = blockIdx.x * blockDim.x + threadIdx.x;
    if (i >= rows * H_) return;
    int row = i >> 11;
    int k   = i & 2047;
    float x = in[i];
    __half h = __float2half_rn(x);
    size_t o = (size_t)(k >> 6) * rows * 64 + (size_t)row * 64 + (k & 63);
    hi[o] = h;
    lo[o] = __float2half_rn(x - __half2float(h));
}

// ---------------------------------------------------------------------------
// All weights: transpose, fp16 hi only -> tiled [k/64][n_total][64]
// ---------------------------------------------------------------------------
__global__ void tsplit_all_kernel(const float* __restrict__ wq,
                                  const float* __restrict__ wk,
                                  const float* __restrict__ wv,
                                  const float* __restrict__ wo,
                                  __half* __restrict__ qkvh,
                                  __half* __restrict__ woh_)
{
    const int seg = blockIdx.z;
    const float* W; int N; int n_base; __half* Th; int n_total;
    if (seg == 0)      { W = wq; N = H_;     n_base = 0;           Th = qkvh; n_total = NQKV; }
    else if (seg == 1) { W = wk; N = KV_DIM; n_base = H_;          Th = qkvh; n_total = NQKV; }
    else if (seg == 2) { W = wv; N = KV_DIM; n_base = H_ + KV_DIM; Th = qkvh; n_total = NQKV; }
    else               { W = wo; N = H_;     n_base = 0;           Th = woh_; n_total = H_; }

    const int n0 = blockIdx.x * 32;
    if (n0 >= N) return;
    const int k0 = blockIdx.y * 32;

    __shared__ float tile[32][33];
    const int tx = threadIdx.x, ty = threadIdx.y;
#pragma unroll
    for (int r = 0; r < 32; r += 8)
        tile[ty + r][tx] = W[(size_t)(k0 + ty + r) * N + n0 + tx];
    __syncthreads();
#pragma unroll
    for (int r = 0; r < 32; r += 8) {
        float v = tile[tx][ty + r];
        int k = k0 + tx;
        int n = n_base + n0 + ty + r;
        size_t o = (size_t)(k >> 6) * n_total * 64 + (size_t)n * 64 + (k & 63);
        Th[o] = __float2half_rn(v);
    }
}

// ---------------------------------------------------------------------------
// fp16 2-term GEMM: D = (Ah+Al)·Bh. 256x128 tile, tiled-K, BK=64, 2-stage.
// qkv_mode=1: epilogue rope (Q hi/lo fp16, K hi fp16) or V transpose (hi fp16)
// qkv_mode=0: fp32 C out (WO projection).
// ---------------------------------------------------------------------------
#define A_BYTES  32768u               // 256 rows * 128 B
#define BB_BYTES 16384u               // 128 rows * 128 B
#define STAGE_B  (2u * A_BYTES + BB_BYTES)   // 81920

__global__ __launch_bounds__(256) void fp16x2_gemm_tiled(
    const __half* __restrict__ Ah, const __half* __restrict__ Al,
    const __half* __restrict__ Bh,
    float* __restrict__ outF, int ldcF,
    __half* __restrict__ qh, __half* __restrict__ ql,
    __half* __restrict__ kh_, __half* __restrict__ vth,
    const float* __restrict__ rc, const float* __restrict__ rs,
    int qkv_mode, int K, int An, int Bn)
{
    extern __shared__ unsigned char smem_raw[];
    const unsigned sbase = smem_u32(smem_raw);

    const int tid  = threadIdx.x;
    const int lane = tid & 31;
    const int warp = tid >> 5;
    const int g = lane >> 2;
    const int t = lane & 3;
    const int wm = (warp & 3) * 64;
    const int wn = (warp >> 2) * 64;

    const int bx   = blockIdx.x;
    const int brow = blockIdx.y * 256;
    const int bcolB = bx * 128;

    const size_t aStride = (size_t)An * 64;
    const size_t bStride = (size_t)Bn * 64;
    const __half* aBaseH = Ah + (size_t)brow * 64;
    const __half* aBaseL = Al + (size_t)brow * 64;
    const __half* bBaseH = Bh + (size_t)bcolB * 64;

#define LOAD_STAGE(s, ch) do {                                                       \
    const unsigned sb = sbase + (unsigned)(s) * STAGE_B;                             \
    const size_t aoffg = (size_t)(ch) * aStride;                                     \
    const size_t boffg = (size_t)(ch) * bStride;                                     \
    _Pragma("unroll")                                                                \
    for (int i_ = 0; i_ < 8; i_++) {                                                 \
        int u  = tid + i_ * 256;                                                     \
        int r_ = u >> 3;                                                             \
        int c8 = u & 7;                                                              \
        unsigned d_ = (unsigned)(r_ * 128 + (((unsigned)c8 ^ ((unsigned)r_ & 7u)) << 4)); \
        size_t gsrc = (size_t)r_ * 64 + (size_t)c8 * 8;                              \
        CP_ASYNC16(sb + d_,           aBaseH + aoffg + gsrc);                        \
        CP_ASYNC16(sb + A_BYTES + d_, aBaseL + aoffg + gsrc);                        \
    }                                                                                \
    _Pragma("unroll")                                                                \
    for (int i_ = 0; i_ < 4; i_++) {                                                 \
        int u  = tid + i_ * 256;                                                     \
        int r_ = u >> 3;                                                             \
        int c8 = u & 7;                                                              \
        unsigned d_ = (unsigned)(r_ * 128 + (((unsigned)c8 ^ ((unsigned)r_ & 7u)) << 4)); \
        size_t gsrc = (size_t)r_ * 64 + (size_t)c8 * 8;                              \
        CP_ASYNC16(sb + 2 * A_BYTES + d_, bBaseH + boffg + gsrc);                    \
    }                                                                                \
} while (0)

    const unsigned arow   = (unsigned)(wm + (lane & 7) + ((lane >> 3) & 1) * 8);
    const unsigned ahi    = (unsigned)((lane >> 4) & 1);
    const unsigned brow_l = (unsigned)(wn + (lane & 7) + ((lane >> 4) & 1) * 8);
    const unsigned bhi    = (unsigned)((lane >> 3) & 1);

    float acc[4][8][4];
#pragma unroll
    for (int i = 0; i < 4; i++)
#pragma unroll
        for (int j = 0; j < 8; j++)
#pragma unroll
            for (int c = 0; c < 4; c++) acc[i][j][c] = 0.f;

    const int niter = K / 64;
    LOAD_STAGE(0, 0); CP_COMMIT();
    LOAD_STAGE(1, 1); CP_COMMIT();

    for (int it = 0; it < niter; it++) {
        CP_WAIT1();
        __syncthreads();
        const unsigned sb = sbase + (unsigned)(it & 1) * STAGE_B;

#pragma unroll
        for (int ks = 0; ks < 64; ks += 16) {
            const unsigned c16a = (unsigned)(ks >> 3) + ahi;
            const unsigned c16b = (unsigned)(ks >> 3) + bhi;
            unsigned ah[4][4], al[4][4], bh[8][2];
#pragma unroll
            for (int i = 0; i < 4; i++) {
                unsigned ra = arow + (unsigned)(i * 16);
                unsigned ad = sb + ra * 128u + ((c16a ^ (ra & 7u)) << 4);
                LDSM_X4(ah[i][0], ah[i][1], ah[i][2], ah[i][3], ad);
                LDSM_X4(al[i][0], al[i][1], al[i][2], al[i][3], ad + A_BYTES);
            }
#pragma unroll
            for (int jp = 0; jp < 4; jp++) {
                unsigned rb = brow_l + (unsigned)(jp * 16);
                unsigned bd = sb + 2 * A_BYTES + rb * 128u + ((c16b ^ (rb & 7u)) << 4);
                LDSM_X4(bh[2 * jp][0], bh[2 * jp][1], bh[2 * jp + 1][0], bh[2 * jp + 1][1], bd);
            }
#pragma unroll
            for (int i = 0; i < 4; i++)
#pragma unroll
                for (int j = 0; j < 8; j++) {
                    float* c = acc[i][j];
                    MMA_F16(c, ah[i][0], ah[i][1], ah[i][2], ah[i][3], bh[j][0], bh[j][1]);
                    MMA_F16(c, al[i][0], al[i][1], al[i][2], al[i][3], bh[j][0], bh[j][1]);
                }
        }
        __syncthreads();
        if (it + 2 < niter) LOAD_STAGE(it & 1, it + 2);
        CP_COMMIT();
    }
#undef LOAD_STAGE

    if (!qkv_mode) {
#pragma unroll
        for (int i = 0; i < 4; i++) {
            const int r0 = brow + wm + i * 16 + g;
#pragma unroll
            for (int j = 0; j < 8; j++) {
                const int cc = bcolB + wn + j * 8 + 2 * t;
                *(float2*)(outF + (size_t)r0 * ldcF + cc)       = make_float2(acc[i][j][0], acc[i][j][1]);
                *(float2*)(outF + (size_t)(r0 + 8) * ldcF + cc) = make_float2(acc[i][j][2], acc[i][j][3]);
            }
        }
        return;
    }

    // QKV epilogue: exchange acc through smem
    __syncthreads();
    float* sep = (float*)smem_raw;     // [256][132] fp32 = 135168 B
#pragma unroll
    for (int i = 0; i < 4; i++) {
        const int r0 = wm + i * 16 + g;
#pragma unroll
        for (int j = 0; j < 8; j++) {
            const int cc = wn + j * 8 + 2 * t;
            sep[r0 * 132 + cc]           = acc[i][j][0];
            sep[r0 * 132 + cc + 1]       = acc[i][j][1];
            sep[(r0 + 8) * 132 + cc]     = acc[i][j][2];
            sep[(r0 + 8) * 132 + cc + 1] = acc[i][j][3];
        }
    }
    __syncthreads();

    if (bx < 20) {
        // Q (bx 0-15): rope + fp16 hi/lo.  K (bx 16-19): rope + fp16 hi only.
        const bool isQ  = bx < 16;
        const int ldo   = isQ ? H_ : KV_DIM;
        const int cbase = isQ ? bx * 128 : (bx - 16) * 128;
        for (int idx = tid; idx < 256 * 32; idx += 256) {
            int r = idx >> 5;
            int d = (idx & 31) * 2;
            int m = brow + r;
            int s = m & (S_ - 1);
            float x1a = sep[r * 132 + d];
            float x1b = sep[r * 132 + d + 1];
            float x2a = sep[r * 132 + d + 64];
            float x2b = sep[r * 132 + d + 65];
            float ca  = rc[s * 64 + d],     cb  = rc[s * 64 + d + 1];
            float sa  = rs[s * 64 + d],     sb_ = rs[s * 64 + d + 1];
            float y1a = x1a * ca - x2a * sa;
            float y1b = x1b * cb - x2b * sb_;
            float y2a = x2a * ca + x1a * sa;
            float y2b = x2b * cb + x1b * sb_;
            size_t o = (size_t)m * ldo + cbase + d;
            if (isQ) {
                __half h1a = __float2half_rn(y1a), h1b = __float2half_rn(y1b);
                __half h2a = __float2half_rn(y2a), h2b = __float2half_rn(y2b);
                *(unsigned*)(qh + o)      = hpack(h1a, h1b);
                *(unsigned*)(ql + o)      = hpack(__float2half_rn(y1a - __half2float(h1a)),
                                                  __float2half_rn(y1b - __half2float(h1b)));
                *(unsigned*)(qh + o + 64) = hpack(h2a, h2b);
                *(unsigned*)(ql + o + 64) = hpack(__float2half_rn(y2a - __half2float(h2a)),
                                                  __float2half_rn(y2b - __half2float(h2b)));
            } else {
                *(unsigned*)(kh_ + o)      = hpack_f(y1a, y1b);
                *(unsigned*)(kh_ + o + 64) = hpack_f(y2a, y2b);
            }
        }
    } else {
        // V tiles (bx 20-23): fused transpose, fp16 hi -> Vt[(b*NKV+kvh)*HD+d][s]
        const int kvh = bx - 20;
        const int b   = brow >> 11;
        const int s0  = brow & (S_ - 1);
        const int d    = tid >> 1;
        const int half = tid & 1;
        __half* Th = vth + (size_t)((b * NKV + kvh) * HD + d) * S_ + s0 + half * 128;
        for (int ss = 0; ss < 128; ss += 2) {
            int r = half * 128 + ss;
            *(unsigned*)(Th + ss) = hpack_f(sep[r * 132 + d], sep[(r + 1) * 132 + d]);
        }
    }
}

// ---------------------------------------------------------------------------
// Flash attention, fp16 2-term: QK = (Qh+Ql)·Kh, PV = (Ph+Pl)·Vh.
// Epilogue writes fp16 hi/lo AO in tiled-K layout.
// ---------------------------------------------------------------------------
#define KROW 136
#define VROW 72

__global__ __launch_bounds__(256) void flash_mma_kernel(
    const __half* __restrict__ Qh, const __half* __restrict__ Ql,
    const __half* __restrict__ Kh, const __half* __restrict__ Vth,
    __half* __restrict__ AOh, __half* __restrict__ AOl)
{
    extern __shared__ __half smem_h[];
    __half* kh = smem_h;                 // [64][KROW]
    __half* vh = kh + 64 * KROW;         // [128][VROW]

    const int qb  = (int)gridDim.x - 1 - (int)blockIdx.x;
    const int bh  = blockIdx.y;
    const int b   = bh >> 4;
    const int h   = bh & 15;
    const int kvh = h >> 2;

    const int tid  = threadIdx.x;
    const int lane = tid & 31;
    const int w    = tid >> 5;
    const int g    = lane >> 2;
    const int t    = lane & 3;
    const int m0   = w * 16;

    unsigned qfh[8][4], qfl[8][4];
    {
        const __half* Qb  = Qh + ((size_t)(b * S_ + qb * 128 + m0)) * H_ + h * HD;
        const __half* Qlb = Ql + ((size_t)(b * S_ + qb * 128 + m0)) * H_ + h * HD;
#pragma unroll
        for (int kc = 0; kc < 8; kc++) {
            int c0 = kc * 16 + 2 * t;
            qfh[kc][0] = *(const unsigned*)(Qb  + (size_t)g * H_ + c0);
            qfh[kc][1] = *(const unsigned*)(Qb  + (size_t)(g + 8) * H_ + c0);
            qfh[kc][2] = *(const unsigned*)(Qb  + (size_t)g * H_ + c0 + 8);
            qfh[kc][3] = *(const unsigned*)(Qb  + (size_t)(g + 8) * H_ + c0 + 8);
            qfl[kc][0] = *(const unsigned*)(Qlb + (size_t)g * H_ + c0);
            qfl[kc][1] = *(const unsigned*)(Qlb + (size_t)(g + 8) * H_ + c0);
            qfl[kc][2] = *(const unsigned*)(Qlb + (size_t)g * H_ + c0 + 8);
            qfl[kc][3] = *(const unsigned*)(Qlb + (size_t)(g + 8) * H_ + c0 + 8);
        }
    }

    float oacc[16][4];
#pragma unroll
    for (int jn = 0; jn < 16; jn++)
#pragma unroll
        for (int c = 0; c < 4; c++) oacc[jn][c] = 0.f;
    float mrow0 = -INFINITY, mrow1 = -INFINITY;
    float lrow0 = 0.f, lrow1 = 0.f;

    const float scale = 0.08838834764831845f;
    const int njt = 2 * qb + 2;

    for (int j = 0; j < njt; j++) {
        __syncthreads();
        {
            const __half* Kb = Kh + (size_t)(b * S_ + j * 64) * KV_DIM + kvh * HD;
#pragma unroll
            for (int it = 0; it < 4; it++) {
                int idx = tid + it * 256;
                int r  = idx >> 4;
                int c8 = (idx & 15) * 8;
                *(uint4*)&kh[r * KROW + c8] = *(const uint4*)(Kb + (size_t)r * KV_DIM + c8);
            }
            const __half* Vb = Vth + ((size_t)((b * NKV + kvh) * HD)) * S_ + j * 64;
#pragma unroll
            for (int it = 0; it < 4; it++) {
                int idx = tid + it * 256;
                int r  = idx >> 3;
                int c8 = (idx & 7) * 8;
                *(uint4*)&vh[r * VROW + c8] = *(const uint4*)(Vb + (size_t)r * S_ + c8);
            }
        }
        __syncthreads();

        float sf[8][4];
#pragma unroll
        for (int jn = 0; jn < 8; jn++)
#pragma unroll
            for (int c = 0; c < 4; c++) sf[jn][c] = 0.f;

#pragma unroll
        for (int jn = 0; jn < 8; jn++) {
            const int n0 = jn * 8;
#pragma unroll
            for (int kc = 0; kc < 8; kc++) {
                const int ck = kc * 16 + 2 * t;
                unsigned b0 = *(const unsigned*)&kh[(n0 + g) * KROW + ck];
                unsigned b1 = *(const unsigned*)&kh[(n0 + g) * KROW + ck + 8];
                float* c = sf[jn];
                MMA_F16(c, qfh[kc][0], qfh[kc][1], qfh[kc][2], qfh[kc][3], b0, b1);
                MMA_F16(c, qfl[kc][0], qfl[kc][1], qfl[kc][2], qfl[kc][3], b0, b1);
            }
        }

        const int row0 = qb * 128 + m0 + g;
        const int row1 = row0 + 8;
        const bool need_mask = (j >= 2 * qb);
#pragma unroll
        for (int jn = 0; jn < 8; jn++) {
            const int cbase = j * 64 + jn * 8 + 2 * t;
#pragma unroll
            for (int c = 0; c < 4; c++) sf[jn][c] *= scale;
            if (need_mask) {
                if (cbase     > row0) sf[jn][0] = -1e30f;
                if (cbase + 1 > row0) sf[jn][1] = -1e30f;
                if (cbase     > row1) sf[jn][2] = -1e30f;
                if (cbase + 1 > row1) sf[jn][3] = -1e30f;
            }
        }

        float mx0 = -INFINITY, mx1 = -INFINITY;
#pragma unroll
        for (int jn = 0; jn < 8; jn++) {
            mx0 = fmaxf(mx0, fmaxf(sf[jn][0], sf[jn][1]));
            mx1 = fmaxf(mx1, fmaxf(sf[jn][2], sf[jn][3]));
        }
        mx0 = fmaxf(mx0, __shfl_xor_sync(0xffffffffu, mx0, 1));
        mx0 = fmaxf(mx0, __shfl_xor_sync(0xffffffffu, mx0, 2));
        mx1 = fmaxf(mx1, __shfl_xor_sync(0xffffffffu, mx1, 1));
        mx1 = fmaxf(mx1, __shfl_xor_sync(0xffffffffu, mx1, 2));
        float mn0 = fmaxf(mrow0, mx0);
        float mn1 = fmaxf(mrow1, mx1);
        float f0 = __expf(mrow0 - mn0);
        float f1 = __expf(mrow1 - mn1);
        mrow0 = mn0; mrow1 = mn1;

        float sum0 = 0.f, sum1 = 0.f;
#pragma unroll
        for (int jn = 0; jn < 8; jn++) {
            sf[jn][0] = __expf(sf[jn][0] - mn0);
            sf[jn][1] = __expf(sf[jn][1] - mn0);
            sf[jn][2] = __expf(sf[jn][2] - mn1);
            sf[jn][3] = __expf(sf[jn][3] - mn1);
            sum0 += sf[jn][0] + sf[jn][1];
            sum1 += sf[jn][2] + sf[jn][3];
        }
        sum0 += __shfl_xor_sync(0xffffffffu, sum0, 1);
        sum0 += __shfl_xor_sync(0xffffffffu, sum0, 2);
        sum1 += __shfl_xor_sync(0xffffffffu, sum1, 1);
        sum1 += __shfl_xor_sync(0xffffffffu, sum1, 2);
        lrow0 = lrow0 * f0 + sum0;
        lrow1 = lrow1 * f1 + sum1;

#pragma unroll
        for (int jn = 0; jn < 16; jn++) {
            oacc[jn][0] *= f0; oacc[jn][1] *= f0;
            oacc[jn][2] *= f1; oacc[jn][3] *= f1;
        }

#pragma unroll
        for (int kc = 0; kc < 4; kc++) {
            const int j0 = 2 * kc, j1 = 2 * kc + 1;
            __half p0a = __float2half_rn(sf[j0][0]), p0b = __float2half_rn(sf[j0][1]);
            __half p1a = __float2half_rn(sf[j0][2]), p1b = __float2half_rn(sf[j0][3]);
            __half p2a = __float2half_rn(sf[j1][0]), p2b = __float2half_rn(sf[j1][1]);
            __half p3a = __float2half_rn(sf[j1][2]), p3b = __float2half_rn(sf[j1][3]);
            unsigned a0h = hpack(p0a, p0b);
            unsigned a1h = hpack(p1a, p1b);
            unsigned a2h = hpack(p2a, p2b);
            unsigned a3h = hpack(p3a, p3b);
            unsigned a0l = hpack_f(sf[j0][0] - __half2float(p0a), sf[j0][1] - __half2float(p0b));
            unsigned a1l = hpack_f(sf[j0][2] - __half2float(p1a), sf[j0][3] - __half2float(p1b));
            unsigned a2l = hpack_f(sf[j1][0] - __half2float(p2a), sf[j1][1] - __half2float(p2b));
            unsigned a3l = hpack_f(sf[j1][2] - __half2float(p3a), sf[j1][3] - __half2float(p3b));
            const int ck = kc * 16 + 2 * t;
#pragma unroll
            for (int jn = 0; jn < 16; jn++) {
                const int n0 = jn * 8;
                unsigned b0 = *(const unsigned*)&vh[(n0 + g) * VROW + ck];
                unsigned b1 = *(const unsigned*)&vh[(n0 + g) * VROW + ck + 8];
                float* c = oacc[jn];
                MMA_F16(c, a0h, a1h, a2h, a3h, b0, b1);
                MMA_F16(c, a0l, a1l, a2l, a3l, b0, b1);
            }
        }
    }

    // epilogue: fp16 split + write tiled-K (k = h*128 + jn*8 + 2t)
    {
        float inv0 = 1.f / lrow0;
        float inv1 = 1.f / lrow1;
        const int row0 = b * S_ + qb * 128 + m0 + g;
        const int row1 = row0 + 8;
#pragma unroll
        for (int jn = 0; jn < 16; jn++) {
            int kk = h * HD + jn * 8 + 2 * t;
            int ch = kk >> 6;
            int wi = kk & 63;
            size_t o0 = (size_t)ch * (M_ * 64) + (size_t)row0 * 64 + wi;
            size_t o1 = (size_t)ch * (M_ * 64) + (size_t)row1 * 64 + wi;
            float v0 = oacc[jn][0] * inv0, v1 = oacc[jn][1] * inv0;
            float v2 = oacc[jn][2] * inv1, v3 = oacc[jn][3] * inv1;
            __half h0 = __float2half_rn(v0), h1 = __float2half_rn(v1);
            __half h2 = __float2half_rn(v2), h3 = __float2half_rn(v3);
            *(unsigned*)(AOh + o0) = hpack(h0, h1);
            *(unsigned*)(AOl + o0) = hpack_f(v0 - __half2float(h0), v1 - __half2float(h1));
            *(unsigned*)(AOh + o1) = hpack(h2, h3);
            *(unsigned*)(AOl + o1) = hpack_f(v2 - __half2float(h2), v3 - __half2float(h3));
        }
    }
}

// ---------------------------------------------------------------------------
extern "C" void kernel_launch(void* const* d_in, const int* in_sizes, int n_in,
                              void* d_out, int out_size)
{
    const float* x  = (const float*)d_in[0];
    const float* rc = (const float*)d_in[1];
    const float* rs = (const float*)d_in[2];
    const float* wq = (const float*)d_in[4];
    const float* wk = (const float*)d_in[5];
    const float* wv = (const float*)d_in[6];
    const float* wo = (const float*)d_in[7];
    float* out = (float*)d_out;

    __half *xh, *xl, *aoh, *aol, *wqkvh, *woh;
    __half *qh, *ql, *kh, *vth;
    cudaGetSymbolAddress((void**)&xh,  g_xh);
    cudaGetSymbolAddress((void**)&xl,  g_xl);
    cudaGetSymbolAddress((void**)&aoh, g_aoh);
    cudaGetSymbolAddress((void**)&aol, g_aol);
    cudaGetSymbolAddress((void**)&wqkvh, g_wqkvh);
    cudaGetSymbolAddress((void**)&woh, g_woh);
    cudaGetSymbolAddress((void**)&qh,  g_Qh);
    cudaGetSymbolAddress((void**)&ql,  g_Ql);
    cudaGetSymbolAddress((void**)&kh,  g_Kh);
    cudaGetSymbolAddress((void**)&vth, g_Vth);

    // Prep
    dim3 tsb(32, 8);
    tsplit_all_kernel<<<dim3(64, 64, 4), tsb>>>(wq, wk, wv, wo, wqkvh, woh);
    split_tiled_kernel<<<(M_ * H_ + 255) / 256, 256>>>(x, xh, xl, M_);

    // Fused QKV projection (fp16 2-term) + rope/V-transpose epilogue
    const int gemm_smem = 2 * (int)STAGE_B;   // 163840
    cudaFuncSetAttribute(fp16x2_gemm_tiled,
                         cudaFuncAttributeMaxDynamicSharedMemorySize, gemm_smem);
    fp16x2_gemm_tiled<<<dim3(NQKV / 128, M_ / 256), 256, gemm_smem>>>(
        xh, xl, wqkvh,
        nullptr, 0, qh, ql, kh, vth, rc, rs,
        1, H_, M_, NQKV);

    // Flash attention (fp16 2-term; writes fp16 tiled AO)
    {
        size_t shmem = (size_t)(64 * KROW + 128 * VROW) * sizeof(__half);
        cudaFuncSetAttribute(flash_mma_kernel,
                             cudaFuncAttributeMaxDynamicSharedMemorySize,
                             (int)shmem);
        flash_mma_kernel<<<dim3(S_ / 128, B_ * NH), 256, shmem>>>(qh, ql, kh, vth, aoh, aol);
    }

    // Output projection (fp16 2-term, fp32 epilogue)
    fp16x2_gemm_tiled<<<dim3(H_ / 128, M_ / 256), 256, gemm_smem>>>(
        aoh, aol, woh,
        out, H_, nullptr, nullptr, nullptr, nullptr, nullptr, nullptr,
        0, H_, M_, H_);
}